// round 5
// baseline (speedup 1.0000x reference)
#include <cuda_runtime.h>
#include <cstdint>

// Problem dims
#define TT 128
#define BB 256
#define II 512
#define HH 1024
#define VV 128
#define OO 64
#define NG 4096   // 4*H

// Decomposition
#define GBLK 2          // batch blocks (128 rows each)
#define HBLK 64         // hidden-unit blocks (16 units each)
#define NCTA (GBLK*HBLK) // 128 CTAs, all co-resident
#define BT 128          // batch tile rows per CTA
#define UT 16           // hidden units per CTA
#define CT 64           // gate columns per CTA (4 gates x 16 units)
#define KC 64           // K chunk
#define NKC (HH/KC)     // 16 chunks per step
#define NTHR 512        // 16 warps: 4x4 warp grid

#define AS_STRIDE 68    // padded smem strides (conflict-free frag reads, 16B aligned)
#define BUF_FLOATS ((BT + CT) * AS_STRIDE)   // one double-buffer slot: A tile + W tile

// smem float offsets
#define OFF_P   0
#define OFF_G   (OFF_P + VV*CT)        // 8192
#define OFF_C   (OFF_G + BT*CT)        // 16384
#define OFF_B0  (OFF_C + BT*UT)        // 18432
#define OFF_B1  (OFF_B0 + BUF_FLOATS)  // 31488
#define OFF_TOK (OFF_B1 + BUF_FLOATS)  // 44544
#define SMEM_FLOATS (OFF_TOK + 136)

// ---- scratch (static device allocations only; no cudaMalloc anywhere) ----
__device__ float g_h[2*BB*HH];        // ping-pong hidden state (tf32-rounded; last step fp32)
__device__ float g_w[NG*HH];          // 16 MB tf32-pre-rounded w_hh
__device__ unsigned g_cnt;
__device__ unsigned g_rel;

__device__ __forceinline__ float tf32r(float x) {
    unsigned v;
    asm("cvt.rna.tf32.f32 %0, %1;" : "=r"(v) : "f"(x));
    return __uint_as_float(v);
}

__device__ __forceinline__ unsigned ld_acq(const unsigned* p) {
    unsigned v;
    asm volatile("ld.acquire.gpu.u32 %0, [%1];" : "=r"(v) : "l"(p) : "memory");
    return v;
}

// Grid-wide barrier; release word is monotonic across launches (graph-replay safe).
__device__ __forceinline__ void grid_sync() {
    __syncthreads();
    if (threadIdx.x == 0) {
        unsigned r0 = ld_acq(&g_rel);
        __threadfence();
        unsigned old = atomicAdd(&g_cnt, 1u);
        if (old == (unsigned)(NCTA - 1)) {
            g_cnt = 0;
            __threadfence();
            atomicAdd(&g_rel, 1u);
        } else {
            while (ld_acq(&g_rel) == r0) { }
        }
    }
    __syncthreads();
}

__device__ __forceinline__ int colIdx(int j, int unit0) {
    return ((j >> 4) << 10) + unit0 + (j & 15);   // gate*1024 + unit
}

__device__ __forceinline__ void mma8(float d[4], const unsigned a[4], const unsigned b[2]) {
    asm volatile(
        "mma.sync.aligned.m16n8k8.row.col.f32.tf32.tf32.f32 "
        "{%0,%1,%2,%3}, {%4,%5,%6,%7}, {%8,%9}, {%0,%1,%2,%3};\n"
        : "+f"(d[0]), "+f"(d[1]), "+f"(d[2]), "+f"(d[3])
        : "r"(a[0]), "r"(a[1]), "r"(a[2]), "r"(a[3]), "r"(b[0]), "r"(b[1]));
}

__device__ __forceinline__ void cpa16(unsigned dst, const float* src) {
    asm volatile("cp.async.cg.shared.global [%0], [%1], 16;" :: "r"(dst), "l"(src));
}
#define CP_COMMIT() asm volatile("cp.async.commit_group;" ::: "memory")
template<int N> __device__ __forceinline__ void cp_wait() {
    asm volatile("cp.async.wait_group %0;" :: "n"(N) : "memory");
}

// Synchronous tile load with tf32 rounding (P-table phase only).
__device__ __forceinline__ void load_tiles_cvt(
    float* As, float* Ws,
    const float* __restrict__ A, int lda,
    const float* __restrict__ W, int ldw,
    int kc, int unit0, int tid)
{
#pragma unroll
    for (int i = 0; i < 4; i++) {               // 2048 float4 / 512 thr
        int id = tid + NTHR * i;
        int r = id >> 4, q = id & 15;
        float4 v = __ldcg((const float4*)(A + (size_t)r * lda + kc + q * 4));
        v.x = tf32r(v.x); v.y = tf32r(v.y); v.z = tf32r(v.z); v.w = tf32r(v.w);
        *(float4*)(As + r * AS_STRIDE + q * 4) = v;
    }
#pragma unroll
    for (int i = 0; i < 2; i++) {               // 1024 float4 / 512 thr
        int id = tid + NTHR * i;
        int r = id >> 4, q = id & 15;
        float4 v = __ldcg((const float4*)(W + (size_t)colIdx(r, unit0) * ldw + kc + q * 4));
        v.x = tf32r(v.x); v.y = tf32r(v.y); v.z = tf32r(v.z); v.w = tf32r(v.w);
        *(float4*)(Ws + r * AS_STRIDE + q * 4) = v;
    }
}

// 4x4 warp grid: each warp computes a 32x16 output tile.
__device__ __forceinline__ void mma_chunk(
    const float* As, const float* Ws, float acc[2][2][4],
    int warp_m, int warp_n, int lane)
{
    int lg = lane >> 2, lt = lane & 3;
#pragma unroll
    for (int kk = 0; kk < KC; kk += 8) {
        unsigned a[2][4], b[2][2];
#pragma unroll
        for (int mb = 0; mb < 2; mb++) {
            int r0 = warp_m * 32 + mb * 16 + lg;
            const float* base = As + r0 * AS_STRIDE + kk + lt;
            a[mb][0] = __float_as_uint(base[0]);
            a[mb][1] = __float_as_uint(base[8 * AS_STRIDE]);
            a[mb][2] = __float_as_uint(base[4]);
            a[mb][3] = __float_as_uint(base[8 * AS_STRIDE + 4]);
        }
#pragma unroll
        for (int nb = 0; nb < 2; nb++) {
            int c0 = warp_n * 16 + nb * 8 + lg;
            const float* base = Ws + c0 * AS_STRIDE + kk + lt;
            b[nb][0] = __float_as_uint(base[0]);
            b[nb][1] = __float_as_uint(base[4]);
        }
#pragma unroll
        for (int mb = 0; mb < 2; mb++)
#pragma unroll
            for (int nb = 0; nb < 2; nb++)
                mma8(acc[mb][nb], a[mb], b[nb]);
    }
}

__global__ void __launch_bounds__(NTHR, 1)
lstm_persistent_kernel(
    const void* __restrict__ inp_raw,    // [T,B] tokens, int32 OR int64 (detected)
    const float* __restrict__ h0,
    const float* __restrict__ c0,
    const float* __restrict__ emb,       // [V,I]
    const float* __restrict__ w_ih,      // [4H,I]
    const float* __restrict__ w_hh,      // [4H,H]
    const float* __restrict__ b_ih,
    const float* __restrict__ b_hh,
    const float* __restrict__ w_out,     // [O,H]
    const float* __restrict__ b_out,
    float* __restrict__ out)             // [B,O]
{
    extern __shared__ float sm[];
    float* Psm   = sm + OFF_P;
    float* gates = sm + OFF_G;
    float* csm   = sm + OFF_C;
    int*   toksm = (int*)(sm + OFF_TOK);

    const int tid  = threadIdx.x;
    const int lane = tid & 31, wid = tid >> 5;
    const int warp_m = wid >> 2, warp_n = wid & 3;  // 4x4
    const int cid = blockIdx.x;
    const int bi = cid >> 6, hi = cid & 63;
    const int b0 = bi * BT;
    const int unit0 = hi * UT;
    const int lg = lane >> 2, lt = lane & 3;

    const unsigned sbase = (unsigned)__cvta_generic_to_shared(sm);

    const int* inp32 = (const int*)inp_raw;
    const long long* inp64 = (const long long*)inp_raw;

    // ---- token dtype detection (int64 little-endian -> all odd words zero) ----
    if (tid == 0) toksm[128] = 0;
    __syncthreads();
    {
        int f = 0;
        for (int i = tid; i < 128; i += NTHR)
            if (inp32[2 * i + 1] != 0) f = 1;
        if (f) atomicOr(&toksm[128], 1);
    }

    // ---- init: tf32-round w_hh -> g_w; tf32-round h0 -> g_h buf0; c0 -> smem ----
    {
        const float4* src = (const float4*)w_hh;
        float4* dst = (float4*)g_w;
        int base = cid * ((NG * HH / 4) / NCTA);
        for (int i = tid; i < (NG * HH / 4) / NCTA; i += NTHR) {
            float4 v = src[base + i];
            v.x = tf32r(v.x); v.y = tf32r(v.y); v.z = tf32r(v.z); v.w = tf32r(v.w);
            dst[base + i] = v;
        }
        const float4* hs = (const float4*)h0;
        float4* hd = (float4*)g_h;
        int hb = cid * ((BB * HH / 4) / NCTA);
        for (int i = tid; i < (BB * HH / 4) / NCTA; i += NTHR) {
            float4 v = hs[hb + i];
            v.x = tf32r(v.x); v.y = tf32r(v.y); v.z = tf32r(v.z); v.w = tf32r(v.w);
            hd[hb + i] = v;
        }
    }
    for (int p = tid; p < BT * UT; p += NTHR) {
        int b = p >> 4, u = p & 15;
        csm[p] = c0[(size_t)(b0 + b) * HH + unit0 + u];
    }
    grid_sync();
    const int tok_is_32 = toksm[128];

    // ---- per-thread cp.async address precompute ----
    // A tile: 2048 float4, 4 per thread. W tile: 1024 float4, 2 per thread.
    int a_src[4];  unsigned a_dst[4];
    int w_src[2];  unsigned w_dst[2];
#pragma unroll
    for (int i = 0; i < 4; i++) {
        int id = tid + NTHR * i;
        int r = id >> 4, q = id & 15;
        a_src[i] = r * HH + q * 4;
        a_dst[i] = (unsigned)((r * AS_STRIDE + q * 4) * 4);
    }
#pragma unroll
    for (int i = 0; i < 2; i++) {
        int id = tid + NTHR * i;
        int r = id >> 4, q = id & 15;
        w_src[i] = colIdx(r, unit0) * HH + q * 4;
        w_dst[i] = (unsigned)(((BT * AS_STRIDE) + r * AS_STRIDE + q * 4) * 4);
    }
    const unsigned bufb[2] = { sbase + OFF_B0 * 4, sbase + OFF_B1 * 4 };

    // ---- P table: P[v][j] = emb[v] . w_ih[col(j)] + b_ih + b_hh ----
    {
        float* As = sm + OFF_B0;
        float* Ws = As + BT * AS_STRIDE;
        float acc[2][2][4];
#pragma unroll
        for (int mb = 0; mb < 2; mb++)
#pragma unroll
            for (int nb = 0; nb < 2; nb++)
#pragma unroll
                for (int e = 0; e < 4; e++) acc[mb][nb][e] = 0.f;

        for (int kc = 0; kc < II; kc += KC) {
            __syncthreads();
            load_tiles_cvt(As, Ws, emb, II, w_ih, II, kc, unit0, tid);
            __syncthreads();
            mma_chunk(As, Ws, acc, warp_m, warp_n, lane);
        }
        __syncthreads();
#pragma unroll
        for (int mb = 0; mb < 2; mb++) {
            int r0 = warp_m * 32 + mb * 16 + lg;
#pragma unroll
            for (int nb = 0; nb < 2; nb++) {
                int c0c = warp_n * 16 + nb * 8 + (lt << 1);
                int gc0 = colIdx(c0c, unit0), gc1 = colIdx(c0c + 1, unit0);
                float bias0 = b_ih[gc0] + b_hh[gc0];
                float bias1 = b_ih[gc1] + b_hh[gc1];
                Psm[r0 * CT + c0c]           = acc[mb][nb][0] + bias0;
                Psm[r0 * CT + c0c + 1]       = acc[mb][nb][1] + bias1;
                Psm[(r0 + 8) * CT + c0c]     = acc[mb][nb][2] + bias0;
                Psm[(r0 + 8) * CT + c0c + 1] = acc[mb][nb][3] + bias1;
            }
        }
        __syncthreads();
    }

    // ---- prefetch W chunk 0 for step 0 (W is h-independent) ----
    {
#pragma unroll
        for (int i = 0; i < 2; i++) cpa16(bufb[0] + w_dst[i], g_w + w_src[i]);
        CP_COMMIT();
    }

    // ---- recurrence: 128 steps, ping-pong h buffers, cp.async double-buffered K-loop ----
    for (int t = 0; t < TT; t++) {
        const float* Ag = g_h + (size_t)(t & 1) * (BB * HH) + (size_t)b0 * HH;
        float* Hout = g_h + (size_t)((t + 1) & 1) * (BB * HH);

        if (tid < BT) {
            toksm[tid] = tok_is_32 ? inp32[t * BB + b0 + tid]
                                   : (int)inp64[(size_t)t * BB + b0 + tid];
        }

        float acc[2][2][4];
#pragma unroll
        for (int mb = 0; mb < 2; mb++)
#pragma unroll
            for (int nb = 0; nb < 2; nb++)
#pragma unroll
                for (int e = 0; e < 4; e++) acc[mb][nb][e] = 0.f;

        // A chunk 0 into buf 0 (W0 already in flight from previous step / preamble)
        {
#pragma unroll
            for (int i = 0; i < 4; i++) cpa16(bufb[0] + a_dst[i], Ag + a_src[i]);
            CP_COMMIT();
        }

#pragma unroll 1
        for (int kc = 0; kc < NKC; kc++) {
            const int cur = kc & 1;
            if (kc < NKC - 1) {
                const int koff = (kc + 1) * KC;
                const unsigned nb_ = bufb[1 - cur];
#pragma unroll
                for (int i = 0; i < 4; i++) cpa16(nb_ + a_dst[i], Ag + a_src[i] + koff);
#pragma unroll
                for (int i = 0; i < 2; i++) cpa16(nb_ + w_dst[i], g_w + w_src[i] + koff);
                CP_COMMIT();
                cp_wait<1>();
            } else {
                cp_wait<0>();
            }
            __syncthreads();
            const float* As = sm + (cur ? OFF_B1 : OFF_B0);
            mma_chunk(As, As + BT * AS_STRIDE, acc, warp_m, warp_n, lane);
            __syncthreads();
        }

        // prefetch W chunk 0 for next step into buf0 (buf0 is dead: last chunk used buf1)
        if (t < TT - 1) {
#pragma unroll
            for (int i = 0; i < 2; i++) cpa16(bufb[0] + w_dst[i], g_w + w_src[i]);
            CP_COMMIT();
        }

        // epilogue: gates = mma + P[token]
#pragma unroll
        for (int mb = 0; mb < 2; mb++) {
            int r0 = warp_m * 32 + mb * 16 + lg;
            int v0 = toksm[r0], v1 = toksm[r0 + 8];
#pragma unroll
            for (int nb = 0; nb < 2; nb++) {
                int c0c = warp_n * 16 + nb * 8 + (lt << 1);
                gates[r0 * CT + c0c]           = acc[mb][nb][0] + Psm[v0 * CT + c0c];
                gates[r0 * CT + c0c + 1]       = acc[mb][nb][1] + Psm[v0 * CT + c0c + 1];
                gates[(r0 + 8) * CT + c0c]     = acc[mb][nb][2] + Psm[v1 * CT + c0c];
                gates[(r0 + 8) * CT + c0c + 1] = acc[mb][nb][3] + Psm[v1 * CT + c0c + 1];
            }
        }
        __syncthreads();

        // pointwise LSTM cell; c in smem; h -> other buffer (tf32-rounded; fp32 last step)
        const bool last = (t == TT - 1);
        for (int p = tid; p < BT * UT; p += NTHR) {
            int b = p >> 4, u = p & 15;
            float gi = gates[b * CT + u];
            float gf = gates[b * CT + 16 + u];
            float gg = gates[b * CT + 32 + u];
            float go = gates[b * CT + 48 + u];
            float iv = 1.f / (1.f + expf(-gi));
            float fv = 1.f / (1.f + expf(-gf));
            float gv = tanhf(gg);
            float ov = 1.f / (1.f + expf(-go));
            float cn = fv * csm[p] + iv * gv;
            float hn = ov * tanhf(cn);
            csm[p] = cn;
            Hout[(size_t)(b0 + b) * HH + unit0 + u] = last ? hn : tf32r(hn);
        }
        grid_sync();
    }

    // ---- output head: h_last (fp32) lives in buffer 0 ----
    if (tid < 128) {
        int id = cid * 128 + tid;
        int b = id >> 6, o = id & 63;
        const float4* hr = (const float4*)(g_h + (size_t)b * HH);
        const float4* wr = (const float4*)(w_out + (size_t)o * HH);
        float s = 0.f;
#pragma unroll 8
        for (int k = 0; k < HH / 4; k++) {
            float4 a = __ldcg(hr + k);
            float4 w = wr[k];
            s += a.x * w.x + a.y * w.y + a.z * w.z + a.w * w.w;
        }
        out[id] = s + b_out[o];
    }
}

extern "C" void kernel_launch(void* const* d_in, const int* in_sizes, int n_in,
                              void* d_out, int out_size) {
    (void)in_sizes; (void)n_in; (void)out_size;
    const size_t smem_bytes = (size_t)SMEM_FLOATS * sizeof(float);
    cudaFuncSetAttribute(lstm_persistent_kernel,
                         cudaFuncAttributeMaxDynamicSharedMemorySize, (int)smem_bytes);
    lstm_persistent_kernel<<<NCTA, NTHR, smem_bytes>>>(
        (const void*)d_in[0],
        (const float*)d_in[1],
        (const float*)d_in[2],
        (const float*)d_in[3],
        (const float*)d_in[4],
        (const float*)d_in[5],
        (const float*)d_in[6],
        (const float*)d_in[7],
        (const float*)d_in[8],
        (const float*)d_in[9],
        (float*)d_out);
}

// round 6
// speedup vs baseline: 1.1113x; 1.1113x over previous
#include <cuda_runtime.h>
#include <cstdint>

// Problem dims
#define TT 128
#define BB 256
#define II 512
#define HH 1024
#define VV 128
#define OO 64
#define NG 4096   // 4*H

// Decomposition
#define GBLK 2          // batch blocks (128 rows each)
#define HBLK 64         // hidden-unit blocks (16 units each)
#define NCTA (GBLK*HBLK) // 128 CTAs, all co-resident
#define BT 128          // batch tile rows per CTA
#define UT 16           // hidden units per CTA
#define CT 64           // gate columns per CTA (4 gates x 16 units)
#define KC 64           // K chunk
#define NKC (HH/KC)     // 16 chunks per step
#define NTHR 256        // 8 warps: 4x2 warp grid (R4 shape - fastest so far)

#define AS_STRIDE 68    // padded smem strides (conflict-free frag reads, 16B aligned)
#define STAGE_FLOATS ((BT + CT) * AS_STRIDE)   // one pipeline stage: A tile + W tile = 13056

// smem float offsets (3-stage pipeline; gates aliases stage B1 - dead at epilogue)
#define OFF_P   0
#define OFF_C   (OFF_P + VV*CT)          // 8192
#define OFF_B0  (OFF_C + BT*UT)          // 10240
#define OFF_B1  (OFF_B0 + STAGE_FLOATS)  // 23296
#define OFF_B2  (OFF_B1 + STAGE_FLOATS)  // 36352
#define OFF_TOK (OFF_B2 + STAGE_FLOATS)  // 49408
#define SMEM_FLOATS (OFF_TOK + 136)      // 49544 floats = 198176 B
#define OFF_G   OFF_B1                   // gates alias

// ---- scratch (static device allocations only) ----
__device__ float g_h[2*BB*HH];        // ping-pong hidden state (tf32-rounded; last step fp32)
__device__ float g_w[NG*HH];          // 16 MB tf32-pre-rounded w_hh
__device__ unsigned g_cnt;
__device__ unsigned g_rel;

__device__ __forceinline__ float tf32r(float x) {
    unsigned v;
    asm("cvt.rna.tf32.f32 %0, %1;" : "=r"(v) : "f"(x));
    return __uint_as_float(v);
}

__device__ __forceinline__ unsigned ld_acq(const unsigned* p) {
    unsigned v;
    asm volatile("ld.acquire.gpu.u32 %0, [%1];" : "=r"(v) : "l"(p) : "memory");
    return v;
}

// Grid-wide barrier; release word is monotonic across launches (graph-replay safe).
__device__ __forceinline__ void grid_sync() {
    __syncthreads();
    if (threadIdx.x == 0) {
        unsigned r0 = ld_acq(&g_rel);
        __threadfence();
        unsigned old = atomicAdd(&g_cnt, 1u);
        if (old == (unsigned)(NCTA - 1)) {
            g_cnt = 0;
            __threadfence();
            atomicAdd(&g_rel, 1u);
        } else {
            while (ld_acq(&g_rel) == r0) { }
        }
    }
    __syncthreads();
}

__device__ __forceinline__ int colIdx(int j, int unit0) {
    return ((j >> 4) << 10) + unit0 + (j & 15);   // gate*1024 + unit
}

__device__ __forceinline__ void mma8(float d[4], const unsigned a[4], const unsigned b[2]) {
    asm volatile(
        "mma.sync.aligned.m16n8k8.row.col.f32.tf32.tf32.f32 "
        "{%0,%1,%2,%3}, {%4,%5,%6,%7}, {%8,%9}, {%0,%1,%2,%3};\n"
        : "+f"(d[0]), "+f"(d[1]), "+f"(d[2]), "+f"(d[3])
        : "r"(a[0]), "r"(a[1]), "r"(a[2]), "r"(a[3]), "r"(b[0]), "r"(b[1]));
}

__device__ __forceinline__ void cpa16(unsigned dst, const float* src) {
    asm volatile("cp.async.cg.shared.global [%0], [%1], 16;" :: "r"(dst), "l"(src));
}
#define CP_COMMIT() asm volatile("cp.async.commit_group;" ::: "memory")
template<int N> __device__ __forceinline__ void cp_wait() {
    asm volatile("cp.async.wait_group %0;" :: "n"(N) : "memory");
}

// Synchronous tile load with tf32 rounding (P-table phase only).
__device__ __forceinline__ void load_tiles_cvt(
    float* As, float* Ws,
    const float* __restrict__ A, int lda,
    const float* __restrict__ W, int ldw,
    int kc, int unit0, int tid)
{
#pragma unroll
    for (int i = 0; i < 8; i++) {
        int id = tid + NTHR * i;
        int r = id >> 4, q = id & 15;
        float4 v = __ldcg((const float4*)(A + (size_t)r * lda + kc + q * 4));
        v.x = tf32r(v.x); v.y = tf32r(v.y); v.z = tf32r(v.z); v.w = tf32r(v.w);
        *(float4*)(As + r * AS_STRIDE + q * 4) = v;
    }
#pragma unroll
    for (int i = 0; i < 4; i++) {
        int id = tid + NTHR * i;
        int r = id >> 4, q = id & 15;
        float4 v = __ldcg((const float4*)(W + (size_t)colIdx(r, unit0) * ldw + kc + q * 4));
        v.x = tf32r(v.x); v.y = tf32r(v.y); v.z = tf32r(v.z); v.w = tf32r(v.w);
        *(float4*)(Ws + r * AS_STRIDE + q * 4) = v;
    }
}

// 4x2 warp grid: each warp computes a 32x32 output tile.
__device__ __forceinline__ void mma_chunk(
    const float* As, const float* Ws, float acc[2][4][4],
    int warp_m, int warp_n, int lane)
{
    int lg = lane >> 2, lt = lane & 3;
#pragma unroll
    for (int kk = 0; kk < KC; kk += 8) {
        unsigned a[2][4], b[4][2];
#pragma unroll
        for (int mb = 0; mb < 2; mb++) {
            int r0 = warp_m * 32 + mb * 16 + lg;
            const float* base = As + r0 * AS_STRIDE + kk + lt;
            a[mb][0] = __float_as_uint(base[0]);
            a[mb][1] = __float_as_uint(base[8 * AS_STRIDE]);
            a[mb][2] = __float_as_uint(base[4]);
            a[mb][3] = __float_as_uint(base[8 * AS_STRIDE + 4]);
        }
#pragma unroll
        for (int nb = 0; nb < 4; nb++) {
            int c0 = warp_n * 32 + nb * 8 + lg;
            const float* base = Ws + c0 * AS_STRIDE + kk + lt;
            b[nb][0] = __float_as_uint(base[0]);
            b[nb][1] = __float_as_uint(base[4]);
        }
#pragma unroll
        for (int mb = 0; mb < 2; mb++)
#pragma unroll
            for (int nb = 0; nb < 4; nb++)
                mma8(acc[mb][nb], a[mb], b[nb]);
    }
}

__global__ void __launch_bounds__(NTHR, 1)
lstm_persistent_kernel(
    const void* __restrict__ inp_raw,    // [T,B] tokens, int32 OR int64 (detected)
    const float* __restrict__ h0,
    const float* __restrict__ c0,
    const float* __restrict__ emb,       // [V,I]
    const float* __restrict__ w_ih,      // [4H,I]
    const float* __restrict__ w_hh,      // [4H,H]
    const float* __restrict__ b_ih,
    const float* __restrict__ b_hh,
    const float* __restrict__ w_out,     // [O,H]
    const float* __restrict__ b_out,
    float* __restrict__ out)             // [B,O]
{
    extern __shared__ float sm[];
    float* Psm   = sm + OFF_P;
    float* gates = sm + OFF_G;           // aliases stage B1 (dead at epilogue)
    float* csm   = sm + OFF_C;
    int*   toksm = (int*)(sm + OFF_TOK);

    const int tid  = threadIdx.x;
    const int lane = tid & 31, wid = tid >> 5;
    const int warp_m = wid >> 1, warp_n = wid & 1;  // 4x2
    const int cid = blockIdx.x;
    const int bi = cid >> 6, hi = cid & 63;
    const int b0 = bi * BT;
    const int unit0 = hi * UT;
    const int lg = lane >> 2, lt = lane & 3;

    const unsigned sbase = (unsigned)__cvta_generic_to_shared(sm);

    const int* inp32 = (const int*)inp_raw;
    const long long* inp64 = (const long long*)inp_raw;

    // ---- token dtype detection (int64 little-endian -> all odd words zero) ----
    if (tid == 0) toksm[128] = 0;
    __syncthreads();
    {
        int f = 0;
        for (int i = tid; i < 128; i += NTHR)
            if (inp32[2 * i + 1] != 0) f = 1;
        if (f) atomicOr(&toksm[128], 1);
    }

    // ---- init: tf32-round w_hh -> g_w; tf32-round h0 -> g_h buf0; c0 -> smem ----
    {
        const float4* src = (const float4*)w_hh;
        float4* dst = (float4*)g_w;
        int base = cid * ((NG * HH / 4) / NCTA);
        for (int i = tid; i < (NG * HH / 4) / NCTA; i += NTHR) {
            float4 v = src[base + i];
            v.x = tf32r(v.x); v.y = tf32r(v.y); v.z = tf32r(v.z); v.w = tf32r(v.w);
            dst[base + i] = v;
        }
        const float4* hs = (const float4*)h0;
        float4* hd = (float4*)g_h;
        int hb = cid * ((BB * HH / 4) / NCTA);
        for (int i = tid; i < (BB * HH / 4) / NCTA; i += NTHR) {
            float4 v = hs[hb + i];
            v.x = tf32r(v.x); v.y = tf32r(v.y); v.z = tf32r(v.z); v.w = tf32r(v.w);
            hd[hb + i] = v;
        }
    }
    for (int p = tid; p < BT * UT; p += NTHR) {
        int b = p >> 4, u = p & 15;
        csm[p] = c0[(size_t)(b0 + b) * HH + unit0 + u];
    }
    grid_sync();
    const int tok_is_32 = toksm[128];

    // ---- per-thread cp.async address precompute ----
    // A tile: 2048 float4, 8 per thread. W tile: 1024 float4, 4 per thread.
    int a_src[8];  unsigned a_dst[8];
    int w_src[4];  unsigned w_dst[4];
#pragma unroll
    for (int i = 0; i < 8; i++) {
        int id = tid + NTHR * i;
        int r = id >> 4, q = id & 15;
        a_src[i] = r * HH + q * 4;
        a_dst[i] = (unsigned)((r * AS_STRIDE + q * 4) * 4);
    }
#pragma unroll
    for (int i = 0; i < 4; i++) {
        int id = tid + NTHR * i;
        int r = id >> 4, q = id & 15;
        w_src[i] = colIdx(r, unit0) * HH + q * 4;
        w_dst[i] = (unsigned)(((BT * AS_STRIDE) + r * AS_STRIDE + q * 4) * 4);
    }
    const unsigned bufb[3] = { sbase + OFF_B0 * 4, sbase + OFF_B1 * 4, sbase + OFF_B2 * 4 };

    // ---- P table: P[v][j] = emb[v] . w_ih[col(j)] + b_ih + b_hh ----
    {
        float* As = sm + OFF_B0;
        float* Ws = As + BT * AS_STRIDE;
        float acc[2][4][4];
#pragma unroll
        for (int mb = 0; mb < 2; mb++)
#pragma unroll
            for (int nb = 0; nb < 4; nb++)
#pragma unroll
                for (int e = 0; e < 4; e++) acc[mb][nb][e] = 0.f;

        for (int kc = 0; kc < II; kc += KC) {
            __syncthreads();
            load_tiles_cvt(As, Ws, emb, II, w_ih, II, kc, unit0, tid);
            __syncthreads();
            mma_chunk(As, Ws, acc, warp_m, warp_n, lane);
        }
        __syncthreads();
#pragma unroll
        for (int mb = 0; mb < 2; mb++) {
            int r0 = warp_m * 32 + mb * 16 + lg;
#pragma unroll
            for (int nb = 0; nb < 4; nb++) {
                int c0c = warp_n * 32 + nb * 8 + (lt << 1);
                int gc0 = colIdx(c0c, unit0), gc1 = colIdx(c0c + 1, unit0);
                float bias0 = b_ih[gc0] + b_hh[gc0];
                float bias1 = b_ih[gc1] + b_hh[gc1];
                Psm[r0 * CT + c0c]           = acc[mb][nb][0] + bias0;
                Psm[r0 * CT + c0c + 1]       = acc[mb][nb][1] + bias1;
                Psm[(r0 + 8) * CT + c0c]     = acc[mb][nb][2] + bias0;
                Psm[(r0 + 8) * CT + c0c + 1] = acc[mb][nb][3] + bias1;
            }
        }
        __syncthreads();
    }

    // ---- issue W chunk 0 for step 0 (UNCOMMITTED; commits with A0 inside the loop) ----
#pragma unroll
    for (int i = 0; i < 4; i++) cpa16(bufb[0] + w_dst[i], g_w + w_src[i]);

    // ---- recurrence: 128 steps; 3-stage cp.async pipeline, ONE barrier per chunk ----
    for (int t = 0; t < TT; t++) {
        const float* Ag = g_h + (size_t)(t & 1) * (BB * HH) + (size_t)b0 * HH;
        float* Hout = g_h + (size_t)((t + 1) & 1) * (BB * HH);

        if (tid < BT) {
            toksm[tid] = tok_is_32 ? inp32[t * BB + b0 + tid]
                                   : (int)inp64[(size_t)t * BB + b0 + tid];
        }

        float acc[2][4][4];
#pragma unroll
        for (int mb = 0; mb < 2; mb++)
#pragma unroll
            for (int nb = 0; nb < 4; nb++)
#pragma unroll
                for (int e = 0; e < 4; e++) acc[mb][nb][e] = 0.f;

        // A chunk 0 into B0 -> commit group {W0, A0}
#pragma unroll
        for (int i = 0; i < 8; i++) cpa16(bufb[0] + a_dst[i], Ag + a_src[i]);
        CP_COMMIT();
        // chunk 1 (A+W) into B1 -> group 1
#pragma unroll
        for (int i = 0; i < 8; i++) cpa16(bufb[1] + a_dst[i], Ag + a_src[i] + KC);
#pragma unroll
        for (int i = 0; i < 4; i++) cpa16(bufb[1] + w_dst[i], g_w + w_src[i] + KC);
        CP_COMMIT();

        // mainloop: wait(k) -> bar -> issue(k+2) -> mma(k)
        int cur = 0;          // stage of chunk kc
        int nxt2 = 2;         // stage of chunk kc+2
#pragma unroll 1
        for (int kc = 0; kc < NKC; kc++) {
            if (kc < NKC - 1) cp_wait<1>(); else cp_wait<0>();
            __syncthreads();
            if (kc + 2 < NKC) {
                const int koff = (kc + 2) * KC;
                const unsigned nb_ = bufb[nxt2];
#pragma unroll
                for (int i = 0; i < 8; i++) cpa16(nb_ + a_dst[i], Ag + a_src[i] + koff);
#pragma unroll
                for (int i = 0; i < 4; i++) cpa16(nb_ + w_dst[i], g_w + w_src[i] + koff);
                CP_COMMIT();
            }
            const float* As = sm + (OFF_B0 + cur * STAGE_FLOATS);
            mma_chunk(As, As + BT * AS_STRIDE, acc, warp_m, warp_n, lane);
            cur = (cur == 2) ? 0 : cur + 1;
            nxt2 = (nxt2 == 2) ? 0 : nxt2 + 1;
        }

        // epilogue: gates = mma + P[token]  (gates aliases B1; B1 has no pending writes)
#pragma unroll
        for (int mb = 0; mb < 2; mb++) {
            int r0 = warp_m * 32 + mb * 16 + lg;
            int v0 = toksm[r0], v1 = toksm[r0 + 8];
#pragma unroll
            for (int nb = 0; nb < 4; nb++) {
                int c0c = warp_n * 32 + nb * 8 + (lt << 1);
                gates[r0 * CT + c0c]           = acc[mb][nb][0] + Psm[v0 * CT + c0c];
                gates[r0 * CT + c0c + 1]       = acc[mb][nb][1] + Psm[v0 * CT + c0c + 1];
                gates[(r0 + 8) * CT + c0c]     = acc[mb][nb][2] + Psm[v1 * CT + c0c];
                gates[(r0 + 8) * CT + c0c + 1] = acc[mb][nb][3] + Psm[v1 * CT + c0c + 1];
            }
        }
        __syncthreads();

        // pointwise LSTM cell; c in smem; h -> other buffer (tf32-rounded; fp32 last step)
        const bool last = (t == TT - 1);
        for (int p = tid; p < BT * UT; p += NTHR) {
            int b = p >> 4, u = p & 15;
            float gi = gates[b * CT + u];
            float gf = gates[b * CT + 16 + u];
            float gg = gates[b * CT + 32 + u];
            float go = gates[b * CT + 48 + u];
            float iv = 1.f / (1.f + expf(-gi));
            float fv = 1.f / (1.f + expf(-gf));
            float gv = tanhf(gg);
            float ov = 1.f / (1.f + expf(-go));
            float cn = fv * csm[p] + iv * gv;
            float hn = ov * tanhf(cn);
            csm[p] = cn;
            Hout[(size_t)(b0 + b) * HH + unit0 + u] = last ? hn : tf32r(hn);
        }

        // issue W chunk 0 for next step into B0 (uncommitted; commits with next A0).
        // B0's last reader was mma(15); all warps passed the epilogue barrier after it.
        if (!last) {
#pragma unroll
            for (int i = 0; i < 4; i++) cpa16(bufb[0] + w_dst[i], g_w + w_src[i]);
        }
        grid_sync();
    }

    // ---- output head: h_last (fp32) lives in buffer 0 ----
    if (tid < 128) {
        int id = cid * 128 + tid;
        int b = id >> 6, o = id & 63;
        const float4* hr = (const float4*)(g_h + (size_t)b * HH);
        const float4* wr = (const float4*)(w_out + (size_t)o * HH);
        float s = 0.f;
#pragma unroll 8
        for (int k = 0; k < HH / 4; k++) {
            float4 a = __ldcg(hr + k);
            float4 w = wr[k];
            s += a.x * w.x + a.y * w.y + a.z * w.z + a.w * w.w;
        }
        out[id] = s + b_out[o];
    }
}

extern "C" void kernel_launch(void* const* d_in, const int* in_sizes, int n_in,
                              void* d_out, int out_size) {
    (void)in_sizes; (void)n_in; (void)out_size;
    const size_t smem_bytes = (size_t)SMEM_FLOATS * sizeof(float);
    cudaFuncSetAttribute(lstm_persistent_kernel,
                         cudaFuncAttributeMaxDynamicSharedMemorySize, (int)smem_bytes);
    lstm_persistent_kernel<<<NCTA, NTHR, smem_bytes>>>(
        (const void*)d_in[0],
        (const float*)d_in[1],
        (const float*)d_in[2],
        (const float*)d_in[3],
        (const float*)d_in[4],
        (const float*)d_in[5],
        (const float*)d_in[6],
        (const float*)d_in[7],
        (const float*)d_in[8],
        (const float*)d_in[9],
        (float*)d_out);
}